// round 4
// baseline (speedup 1.0000x reference)
#include <cuda_runtime.h>

// ---------------------------------------------------------------------------
// Problem constants
// ---------------------------------------------------------------------------
constexpr int Bb  = 2048;
constexpr int Nn  = 8;
constexpr int Tt  = 20;
constexpr int Mm  = Bb * Nn;        // 16384 sequences
constexpr int ES  = 64;
constexpr int HS  = 128;
constexpr int G3  = 3 * HS;         // 384
constexpr int RT  = Mm * Tt;        // 327680 rows (m*T + t)
constexpr int WTP = 386;            // smem pitch for k-major weight tiles
constexpr int OUT0 = Mm * 64;       // first output section ("out"), 1048576 floats

// Scratch as device globals (no runtime allocation allowed)
__device__ float g_xe[(size_t)RT * ES];   //  84 MB embedded inputs
__device__ float g_gi[(size_t)RT * G3];   // 503 MB input-gate preactivations
__device__ float g_ys[(size_t)RT * HS];   // 168 MB layer outputs (reused per layer)

typedef unsigned long long ULL;

// f32x2 packed-FMA helpers (full fp32 rate on sm_103a requires fma.rn.f32x2)
__device__ __forceinline__ ULL pack_dup(float x) {
    ULL r; asm("mov.b64 %0, {%1, %1};" : "=l"(r) : "f"(x)); return r;
}
__device__ __forceinline__ void fma2(ULL& d, ULL a, ULL b) {
    asm("fma.rn.f32x2 %0, %1, %2, %0;" : "+l"(d) : "l"(a), "l"(b));
}
__device__ __forceinline__ float2 unpk(ULL v) {
    float2 f; asm("mov.b64 {%0, %1}, %2;" : "=f"(f.x), "=f"(f.y) : "l"(v)); return f;
}
__device__ __forceinline__ float sigm(float x) { return 1.0f / (1.0f + __expf(-x)); }
__device__ __forceinline__ float tanh_(float x) { return 1.0f - 2.0f / (__expf(2.0f * x) + 1.0f); }

// ---------------------------------------------------------------------------
// Kernel 1: embedding  xe = relu((x + pe) @ emb_W^T + emb_b)
// ---------------------------------------------------------------------------
__global__ __launch_bounds__(256) void embed_kernel(
    const float* __restrict__ x, const float* __restrict__ pea,
    const float* __restrict__ pet, const float* __restrict__ W,
    const float* __restrict__ b)
{
    int gid = blockIdx.x * 256 + threadIdx.x;
    if (gid >= RT * ES) return;
    int e  = gid & 63;
    int mt = gid >> 6;           // m*Tt + t
    int t  = mt % Tt;
    int n  = (mt / Tt) & 7;
    float pe = pet[t] + pea[n];
    float x0 = x[(size_t)mt * 2]     + pe;
    float x1 = x[(size_t)mt * 2 + 1] + pe;
    float v = fmaf(x0, W[e * 2], fmaf(x1, W[e * 2 + 1], b[e]));
    g_xe[gid] = fmaxf(v, 0.0f);
}

// ---------------------------------------------------------------------------
// Kernel 2: gi GEMM   gi[r,:] = xs[r,:] @ Wih^T + bih
// 256 threads, 128 rows/CTA (4 subtiles of 32). Thread: 8 rows x 3 gate-pairs.
// K=64 reads g_xe (layer 0), K=128 reads g_ys (layers 1,2).
// ---------------------------------------------------------------------------
template <int K>
__global__ __launch_bounds__(256) void gi_gemm(
    const float* __restrict__ Wih, const float* __restrict__ bih)
{
    extern __shared__ float sm[];
    float* Wt = sm;             // [K][WTP]
    float* xT = sm + K * WTP;   // [K][34]

    const float* __restrict__ xs = (K == 64) ? g_xe : g_ys;
    int tid = threadIdx.x;

    // transpose Wih (G3 x K) -> Wt[k][g]
    for (int idx = tid; idx < G3 * K; idx += 256) {
        int g = idx / K, k = idx % K;
        Wt[k * WTP + g] = Wih[idx];
    }

    int rg = tid >> 6;          // row-group 0..3 (8 rows each)
    int cp = tid & 63;          // column-pair 0..63
    int c2 = cp * 2;
    int r0 = rg * 8;

    const float2 bR = *(const float2*)(bih + c2);
    const float2 bZ = *(const float2*)(bih + 128 + c2);
    const float2 bN = *(const float2*)(bih + 256 + c2);

    int row00 = blockIdx.x * 128;

    for (int st = 0; st < 4; ++st) {
        int row0 = row00 + st * 32;
        __syncthreads();  // Wt ready (st=0) / previous xT reads done (st>0)
        for (int idx = tid; idx < 32 * K; idx += 256) {
            int r = idx / K, k = idx % K;
            xT[k * 34 + r] = xs[(size_t)row0 * K + idx];
        }
        __syncthreads();

        ULL aR[8], aZ[8], aN[8];
#pragma unroll
        for (int j = 0; j < 8; ++j) { aR[j] = 0; aZ[j] = 0; aN[j] = 0; }

#pragma unroll 4
        for (int k = 0; k < K; ++k) {
            const float* wrow = Wt + k * WTP;
            ULL wr = *(const ULL*)(wrow + c2);
            ULL wz = *(const ULL*)(wrow + 128 + c2);
            ULL wn = *(const ULL*)(wrow + 256 + c2);
            const float* hrow = xT + k * 34 + r0;
#pragma unroll
            for (int jj = 0; jj < 4; ++jj) {
                float2 hp = *(const float2*)(hrow + 2 * jj);
                ULL h0 = pack_dup(hp.x);
                ULL h1 = pack_dup(hp.y);
                fma2(aR[2*jj  ], h0, wr); fma2(aZ[2*jj  ], h0, wz); fma2(aN[2*jj  ], h0, wn);
                fma2(aR[2*jj+1], h1, wr); fma2(aZ[2*jj+1], h1, wz); fma2(aN[2*jj+1], h1, wn);
            }
        }

#pragma unroll
        for (int j = 0; j < 8; ++j) {
            size_t row = (size_t)(row0 + r0 + j);
            float* go = g_gi + row * G3;
            float2 vR = unpk(aR[j]); vR.x += bR.x; vR.y += bR.y;
            float2 vZ = unpk(aZ[j]); vZ.x += bZ.x; vZ.y += bZ.y;
            float2 vN = unpk(aN[j]); vN.x += bN.x; vN.y += bN.y;
            *(float2*)(go + c2)       = vR;
            *(float2*)(go + 128 + c2) = vZ;
            *(float2*)(go + 256 + c2) = vN;
        }
    }
}

// ---------------------------------------------------------------------------
// Kernel 3: GRU recurrent scan for one layer.
// 512 CTAs x 256 threads x 32 rows; all 20 steps on-chip.
// smem: Whh^T [128][WTP] fp32 + h tile [128][34] (h-dim major, row minor).
// ---------------------------------------------------------------------------
__global__ __launch_bounds__(256) void scan_kernel(
    const float* __restrict__ Whh, const float* __restrict__ bhh,
    float* __restrict__ hid)
{
    extern __shared__ float sm[];
    float* Wt = sm;              // [128][WTP]
    float* hT = sm + HS * WTP;   // [128][34]

    int tid = threadIdx.x;
    for (int idx = tid; idx < G3 * HS; idx += 256) {
        int g = idx >> 7, k = idx & 127;
        Wt[k * WTP + g] = Whh[idx];
    }
    for (int idx = tid; idx < HS * 34; idx += 256) hT[idx] = 0.0f;  // h0 = 0

    int rg = tid >> 6;           // 0..3 (8 rows each)
    int cp = tid & 63;
    int c2 = cp * 2;
    int r0 = rg * 8;

    const float2 bR = *(const float2*)(bhh + c2);
    const float2 bZ = *(const float2*)(bhh + 128 + c2);
    const float2 bN = *(const float2*)(bhh + 256 + c2);

    int m0 = blockIdx.x * 32;
    __syncthreads();

    for (int t = 0; t < Tt; ++t) {
        ULL aR[8], aZ[8], aN[8];
#pragma unroll
        for (int j = 0; j < 8; ++j) { aR[j] = 0; aZ[j] = 0; aN[j] = 0; }

#pragma unroll 4
        for (int k = 0; k < HS; ++k) {
            const float* wrow = Wt + k * WTP;
            ULL wr = *(const ULL*)(wrow + c2);
            ULL wz = *(const ULL*)(wrow + 128 + c2);
            ULL wn = *(const ULL*)(wrow + 256 + c2);
            const float* hrow = hT + k * 34 + r0;
#pragma unroll
            for (int jj = 0; jj < 4; ++jj) {
                float2 hp = *(const float2*)(hrow + 2 * jj);
                ULL h0 = pack_dup(hp.x);
                ULL h1 = pack_dup(hp.y);
                fma2(aR[2*jj  ], h0, wr); fma2(aZ[2*jj  ], h0, wz); fma2(aN[2*jj  ], h0, wn);
                fma2(aR[2*jj+1], h1, wr); fma2(aZ[2*jj+1], h1, wz); fma2(aN[2*jj+1], h1, wn);
            }
        }
        __syncthreads();   // all hT reads of this step done

        // Gates + state update. This thread owns columns {c2,c2+1} of rows
        // r0..r0+7 in hT — nobody else touches them until next k-loop.
#pragma unroll
        for (int j = 0; j < 8; ++j) {
            int r = r0 + j;
            size_t rbase = (size_t)(m0 + r) * Tt + t;
            const float* gp = g_gi + rbase * G3;
            float2 giR = *(const float2*)(gp + c2);
            float2 giZ = *(const float2*)(gp + 128 + c2);
            float2 giN = *(const float2*)(gp + 256 + c2);
            float2 ghR = unpk(aR[j]);
            float2 ghZ = unpk(aZ[j]);
            float2 ghN = unpk(aN[j]);
            float rv0 = sigm(giR.x + ghR.x + bR.x);
            float rv1 = sigm(giR.y + ghR.y + bR.y);
            float zv0 = sigm(giZ.x + ghZ.x + bZ.x);
            float zv1 = sigm(giZ.y + ghZ.y + bZ.y);
            float nv0 = tanh_(giN.x + rv0 * (ghN.x + bN.x));
            float nv1 = tanh_(giN.y + rv1 * (ghN.y + bN.y));
            float h0 = hT[c2 * 34 + r];
            float h1 = hT[(c2 + 1) * 34 + r];
            float hn0 = (1.0f - zv0) * nv0 + zv0 * h0;
            float hn1 = (1.0f - zv1) * nv1 + zv1 * h1;
            *(float2*)(g_ys + rbase * HS + c2) = make_float2(hn0, hn1);
            hT[c2 * 34 + r]       = hn0;
            hT[(c2 + 1) * 34 + r] = hn1;
        }
        __syncthreads();   // new h visible before next k-loop
    }

    // hidden output: final h for rows with m % 8 == 7 (agent n = 7).
    // Each thread's row j=7 qualifies (m0 % 32 == 0, r0 % 8 == 0).
    {
        int r = r0 + 7;
        int m = m0 + r;
        int b = m >> 3;
        float2 hv = make_float2(hT[c2 * 34 + r], hT[(c2 + 1) * 34 + r]);
        *(float2*)(hid + (size_t)b * HS + c2) = hv;
    }
}

// ---------------------------------------------------------------------------
// Kernel 4: output projection  out[m, e] = ys_last[m, :] @ out_W[e, :] + out_b[e]
// ---------------------------------------------------------------------------
__global__ __launch_bounds__(256) void out_kernel(
    const float* __restrict__ oW, const float* __restrict__ ob,
    float* __restrict__ out)
{
    __shared__ float sW[128 * 64];   // transposed [k][e]
    int tid = threadIdx.x;
    for (int idx = tid; idx < 64 * 128; idx += 256) {
        int e = idx >> 7, k = idx & 127;
        sW[k * 64 + e] = oW[idx];
    }
    __syncthreads();
    int gid = blockIdx.x * 256 + tid;       // gid = m*64 + e
    int e = gid & 63;
    int m = gid >> 6;
    const float* ys = g_ys + ((size_t)m * Tt + (Tt - 1)) * HS;
    float acc = ob[e];
#pragma unroll 8
    for (int k = 0; k < 128; ++k) acc = fmaf(ys[k], sW[k * 64 + e], acc);
    out[gid] = acc;
}

// ---------------------------------------------------------------------------
// Launch
// ---------------------------------------------------------------------------
extern "C" void kernel_launch(void* const* d_in, const int* in_sizes, int n_in,
                              void* d_out, int out_size) {
    const float* x    = (const float*)d_in[0];
    const float* pea  = (const float*)d_in[1];
    const float* pet  = (const float*)d_in[2];
    const float* embW = (const float*)d_in[3];
    const float* embB = (const float*)d_in[4];
    const float* Wih0 = (const float*)d_in[5];
    const float* WihR = (const float*)d_in[6];   // (2, 384, 128)
    const float* Whh  = (const float*)d_in[7];   // (3, 384, 128)
    const float* bih  = (const float*)d_in[8];   // (3, 384)
    const float* bhh  = (const float*)d_in[9];   // (3, 384)
    const float* outW = (const float*)d_in[10];  // (64, 128)
    const float* outB = (const float*)d_in[11];

    float* out = (float*)d_out;                  // [Mm*64]
    float* hid = out + OUT0;                     // [3][Bb][HS]

    const int smem64  = 64  * WTP * 4 + 64  * 34 * 4;   // 107520
    const int smem128 = 128 * WTP * 4 + 128 * 34 * 4;   // 215040
    cudaFuncSetAttribute(gi_gemm<64>,  cudaFuncAttributeMaxDynamicSharedMemorySize, smem64);
    cudaFuncSetAttribute(gi_gemm<128>, cudaFuncAttributeMaxDynamicSharedMemorySize, smem128);
    cudaFuncSetAttribute(scan_kernel,  cudaFuncAttributeMaxDynamicSharedMemorySize, smem128);

    embed_kernel<<<(RT * ES) / 256, 256>>>(x, pea, pet, embW, embB);

    // layer 0
    gi_gemm<64><<<RT / 128, 256, smem64>>>(Wih0, bih);
    scan_kernel<<<Mm / 32, 256, smem128>>>(Whh, bhh, hid);
    // layer 1
    gi_gemm<128><<<RT / 128, 256, smem128>>>(WihR, bih + G3);
    scan_kernel<<<Mm / 32, 256, smem128>>>(Whh + (size_t)G3 * HS, bhh + G3,
                                           hid + (size_t)Bb * HS);
    // layer 2
    gi_gemm<128><<<RT / 128, 256, smem128>>>(WihR + (size_t)G3 * HS, bih + 2 * G3);
    scan_kernel<<<Mm / 32, 256, smem128>>>(Whh + (size_t)2 * G3 * HS, bhh + 2 * G3,
                                           hid + (size_t)2 * Bb * HS);

    out_kernel<<<(Mm * 64) / 256, 256>>>(outW, outB, out);
}

// round 5
// speedup vs baseline: 1.0276x; 1.0276x over previous
#include <cuda_runtime.h>

// ---------------------------------------------------------------------------
// Problem constants
// ---------------------------------------------------------------------------
constexpr int Bb  = 2048;
constexpr int Nn  = 8;
constexpr int Tt  = 20;
constexpr int Mm  = Bb * Nn;        // 16384 sequences
constexpr int ES  = 64;
constexpr int HS  = 128;
constexpr int G3  = 3 * HS;         // 384
constexpr int RT  = Mm * Tt;        // 327680 rows (m*T + t)
constexpr int WTP = 386;            // weight tile pitch (conflict-free transpose)
constexpr int DP  = 66;             // duplicated-activation tile pitch
constexpr int OUT0 = Mm * 64;       // first output section ("out")

// Scratch as device globals (no runtime allocation allowed)
__device__ float g_xe[(size_t)RT * ES];   //  84 MB embedded inputs
__device__ float g_gi[(size_t)RT * G3];   // 503 MB input-gate preactivations
__device__ float g_ys[(size_t)RT * HS];   // 168 MB layer outputs (reused per layer)

typedef unsigned long long ULL;

// packed f32x2 FMA (full fp32 rate on sm_103a requires fma.rn.f32x2)
__device__ __forceinline__ void fma2(ULL& d, ULL a, ULL b) {
    asm("fma.rn.f32x2 %0, %1, %2, %0;" : "+l"(d) : "l"(a), "l"(b));
}
__device__ __forceinline__ float2 unpk(ULL v) {
    float2 f; asm("mov.b64 {%0, %1}, %2;" : "=f"(f.x), "=f"(f.y) : "l"(v)); return f;
}
__device__ __forceinline__ float sigm(float x) { return 1.0f / (1.0f + __expf(-x)); }
__device__ __forceinline__ float tanh_(float x) { return 1.0f - 2.0f / (__expf(2.0f * x) + 1.0f); }

// ---------------------------------------------------------------------------
// Kernel 1: embedding  xe = relu((x + pe) @ emb_W^T + emb_b)
// ---------------------------------------------------------------------------
__global__ __launch_bounds__(256) void embed_kernel(
    const float* __restrict__ x, const float* __restrict__ pea,
    const float* __restrict__ pet, const float* __restrict__ W,
    const float* __restrict__ b)
{
    int gid = blockIdx.x * 256 + threadIdx.x;
    if (gid >= RT * ES) return;
    int e  = gid & 63;
    int mt = gid >> 6;           // m*Tt + t
    int t  = mt % Tt;
    int n  = (mt / Tt) & 7;
    float pe = pet[t] + pea[n];
    float x0 = x[(size_t)mt * 2]     + pe;
    float x1 = x[(size_t)mt * 2 + 1] + pe;
    float v = fmaf(x0, W[e * 2], fmaf(x1, W[e * 2 + 1], b[e]));
    g_xe[gid] = fmaxf(v, 0.0f);
}

// ---------------------------------------------------------------------------
// Kernel 2: gi GEMM   gi[r,:] = xs[r,:] @ Wih^T + bih
// 512 threads, 128 rows/CTA (4 subtiles of 32). Thread: 4 rows x 3 gate-pairs.
// Activation tile stored DUPLICATED (xT[k][2r]=xT[k][2r+1]) so the f32x2
// broadcast operand is a single LDS.64 — no mov.b64 duplication in the k-loop.
// ---------------------------------------------------------------------------
template <int K>
__global__ __launch_bounds__(512) void gi_gemm(
    const float* __restrict__ Wih, const float* __restrict__ bih)
{
    extern __shared__ float sm[];
    float* Wt = sm;             // [K][WTP]
    float* xT = sm + K * WTP;   // [K][DP]  (duplicated rows)

    const float* __restrict__ xs = (K == 64) ? g_xe : g_ys;
    int tid = threadIdx.x;

    // transpose Wih (G3 x K) -> Wt[k][g]  (conflict-free: pitch 386)
    for (int idx = tid; idx < G3 * K; idx += 512) {
        int g = idx / K, k = idx % K;
        Wt[k * WTP + g] = Wih[idx];
    }

    int rg = tid >> 6;          // row-group 0..7 (4 rows each)
    int cp = tid & 63;          // column-pair 0..63
    int c2 = cp * 2;
    int r0 = rg * 4;

    const float2 bR = *(const float2*)(bih + c2);
    const float2 bZ = *(const float2*)(bih + 128 + c2);
    const float2 bN = *(const float2*)(bih + 256 + c2);

    int row00 = blockIdx.x * 128;

    for (int st = 0; st < 4; ++st) {
        int row0 = row00 + st * 32;
        __syncthreads();  // Wt ready (st=0) / previous xT reads done (st>0)
        for (int idx = tid; idx < 32 * K; idx += 512) {
            int r = idx / K, k = idx % K;
            float v = xs[(size_t)row0 * K + idx];
            *(float2*)(xT + k * DP + 2 * r) = make_float2(v, v);
        }
        __syncthreads();

        ULL aR[4], aZ[4], aN[4];
#pragma unroll
        for (int j = 0; j < 4; ++j) { aR[j] = 0; aZ[j] = 0; aN[j] = 0; }

#pragma unroll 4
        for (int k = 0; k < K; ++k) {
            const float* wrow = Wt + k * WTP;
            ULL wr = *(const ULL*)(wrow + c2);
            ULL wz = *(const ULL*)(wrow + 128 + c2);
            ULL wn = *(const ULL*)(wrow + 256 + c2);
            const float* hrow = xT + k * DP + 2 * r0;
            ULL h0 = *(const ULL*)(hrow);
            ULL h1 = *(const ULL*)(hrow + 2);
            ULL h2 = *(const ULL*)(hrow + 4);
            ULL h3 = *(const ULL*)(hrow + 6);
            fma2(aR[0], h0, wr); fma2(aZ[0], h0, wz); fma2(aN[0], h0, wn);
            fma2(aR[1], h1, wr); fma2(aZ[1], h1, wz); fma2(aN[1], h1, wn);
            fma2(aR[2], h2, wr); fma2(aZ[2], h2, wz); fma2(aN[2], h2, wn);
            fma2(aR[3], h3, wr); fma2(aZ[3], h3, wz); fma2(aN[3], h3, wn);
        }

#pragma unroll
        for (int j = 0; j < 4; ++j) {
            size_t row = (size_t)(row0 + r0 + j);
            float* go = g_gi + row * G3;
            float2 vR = unpk(aR[j]); vR.x += bR.x; vR.y += bR.y;
            float2 vZ = unpk(aZ[j]); vZ.x += bZ.x; vZ.y += bZ.y;
            float2 vN = unpk(aN[j]); vN.x += bN.x; vN.y += bN.y;
            *(float2*)(go + c2)       = vR;
            *(float2*)(go + 128 + c2) = vZ;
            *(float2*)(go + 256 + c2) = vN;
        }
    }
}

// ---------------------------------------------------------------------------
// Kernel 3: GRU recurrent scan for one layer.
// 512 CTAs x 512 threads x 32 rows; all 20 steps on-chip.
// smem: Whh^T [128][WTP] fp32 + duplicated h tile [128][DP].
// Each thread keeps its own h (4 rows x 2 cols) in registers across steps.
// ---------------------------------------------------------------------------
__global__ __launch_bounds__(512) void scan_kernel(
    const float* __restrict__ Whh, const float* __restrict__ bhh,
    float* __restrict__ hid)
{
    extern __shared__ float sm[];
    float* Wt = sm;              // [128][WTP]
    float* hT = sm + HS * WTP;   // [128][DP]  (duplicated rows)

    int tid = threadIdx.x;
    for (int idx = tid; idx < G3 * HS; idx += 512) {
        int g = idx >> 7, k = idx & 127;
        Wt[k * WTP + g] = Whh[idx];
    }
    for (int idx = tid; idx < HS * DP; idx += 512) hT[idx] = 0.0f;  // h0 = 0

    int rg = tid >> 6;           // 0..7 (4 rows each)
    int cp = tid & 63;
    int c2 = cp * 2;
    int r0 = rg * 4;

    const float2 bR = *(const float2*)(bhh + c2);
    const float2 bZ = *(const float2*)(bhh + 128 + c2);
    const float2 bN = *(const float2*)(bhh + 256 + c2);

    float2 hreg[4];
#pragma unroll
    for (int j = 0; j < 4; ++j) hreg[j] = make_float2(0.0f, 0.0f);

    int m0 = blockIdx.x * 32;
    __syncthreads();

    for (int t = 0; t < Tt; ++t) {
        ULL aR[4], aZ[4], aN[4];
#pragma unroll
        for (int j = 0; j < 4; ++j) { aR[j] = 0; aZ[j] = 0; aN[j] = 0; }

#pragma unroll 4
        for (int k = 0; k < HS; ++k) {
            const float* wrow = Wt + k * WTP;
            ULL wr = *(const ULL*)(wrow + c2);
            ULL wz = *(const ULL*)(wrow + 128 + c2);
            ULL wn = *(const ULL*)(wrow + 256 + c2);
            const float* hrow = hT + k * DP + 2 * r0;
            ULL h0 = *(const ULL*)(hrow);
            ULL h1 = *(const ULL*)(hrow + 2);
            ULL h2 = *(const ULL*)(hrow + 4);
            ULL h3 = *(const ULL*)(hrow + 6);
            fma2(aR[0], h0, wr); fma2(aZ[0], h0, wz); fma2(aN[0], h0, wn);
            fma2(aR[1], h1, wr); fma2(aZ[1], h1, wz); fma2(aN[1], h1, wn);
            fma2(aR[2], h2, wr); fma2(aZ[2], h2, wz); fma2(aN[2], h2, wn);
            fma2(aR[3], h3, wr); fma2(aZ[3], h3, wz); fma2(aN[3], h3, wn);
        }
        __syncthreads();   // all hT reads of this step done

#pragma unroll
        for (int j = 0; j < 4; ++j) {
            int r = r0 + j;
            size_t rbase = (size_t)(m0 + r) * Tt + t;
            const float* gp = g_gi + rbase * G3;
            float2 giR = *(const float2*)(gp + c2);
            float2 giZ = *(const float2*)(gp + 128 + c2);
            float2 giN = *(const float2*)(gp + 256 + c2);
            float2 ghR = unpk(aR[j]);
            float2 ghZ = unpk(aZ[j]);
            float2 ghN = unpk(aN[j]);
            float rv0 = sigm(giR.x + ghR.x + bR.x);
            float rv1 = sigm(giR.y + ghR.y + bR.y);
            float zv0 = sigm(giZ.x + ghZ.x + bZ.x);
            float zv1 = sigm(giZ.y + ghZ.y + bZ.y);
            float nv0 = tanh_(giN.x + rv0 * (ghN.x + bN.x));
            float nv1 = tanh_(giN.y + rv1 * (ghN.y + bN.y));
            float hn0 = (1.0f - zv0) * nv0 + zv0 * hreg[j].x;
            float hn1 = (1.0f - zv1) * nv1 + zv1 * hreg[j].y;
            hreg[j] = make_float2(hn0, hn1);
            *(float2*)(g_ys + rbase * HS + c2) = hreg[j];
            // duplicated store so next step's k-loop gets (h,h) in one LDS.64
            *(float2*)(hT + c2 * DP + 2 * r)       = make_float2(hn0, hn0);
            *(float2*)(hT + (c2 + 1) * DP + 2 * r) = make_float2(hn1, hn1);
        }
        __syncthreads();   // new h visible before next k-loop
    }

    // hidden output: final h of rows with m % 8 == 7 (agent n = 7).
    // r = rg*4+3 == 7 (mod 8)  <=>  rg odd.
    if (rg & 1) {
        int m = m0 + r0 + 3;
        int b = m >> 3;
        *(float2*)(hid + (size_t)b * HS + c2) = hreg[3];
    }
}

// ---------------------------------------------------------------------------
// Kernel 4: output projection  out[m, e] = ys_last[m, :] @ out_W[e, :] + out_b[e]
// ---------------------------------------------------------------------------
__global__ __launch_bounds__(256) void out_kernel(
    const float* __restrict__ oW, const float* __restrict__ ob,
    float* __restrict__ out)
{
    __shared__ float sW[128 * 64];   // transposed [k][e]
    int tid = threadIdx.x;
    for (int idx = tid; idx < 64 * 128; idx += 256) {
        int e = idx >> 7, k = idx & 127;
        sW[k * 64 + e] = oW[idx];
    }
    __syncthreads();
    int gid = blockIdx.x * 256 + tid;       // gid = m*64 + e
    int e = gid & 63;
    int m = gid >> 6;
    const float* ys = g_ys + ((size_t)m * Tt + (Tt - 1)) * HS;
    float acc = ob[e];
#pragma unroll 8
    for (int k = 0; k < 128; ++k) acc = fmaf(ys[k], sW[k * 64 + e], acc);
    out[gid] = acc;
}

// ---------------------------------------------------------------------------
// Launch
// ---------------------------------------------------------------------------
extern "C" void kernel_launch(void* const* d_in, const int* in_sizes, int n_in,
                              void* d_out, int out_size) {
    const float* x    = (const float*)d_in[0];
    const float* pea  = (const float*)d_in[1];
    const float* pet  = (const float*)d_in[2];
    const float* embW = (const float*)d_in[3];
    const float* embB = (const float*)d_in[4];
    const float* Wih0 = (const float*)d_in[5];
    const float* WihR = (const float*)d_in[6];   // (2, 384, 128)
    const float* Whh  = (const float*)d_in[7];   // (3, 384, 128)
    const float* bih  = (const float*)d_in[8];   // (3, 384)
    const float* bhh  = (const float*)d_in[9];   // (3, 384)
    const float* outW = (const float*)d_in[10];  // (64, 128)
    const float* outB = (const float*)d_in[11];

    float* out = (float*)d_out;                  // [Mm*64]
    float* hid = out + OUT0;                     // [3][Bb][HS]

    const int smem64  = 64  * WTP * 4 + 64  * DP * 4;   // 115712 (2 CTAs/SM)
    const int smem128 = 128 * WTP * 4 + 128 * DP * 4;   // 231424
    cudaFuncSetAttribute(gi_gemm<64>,  cudaFuncAttributeMaxDynamicSharedMemorySize, smem64);
    cudaFuncSetAttribute(gi_gemm<128>, cudaFuncAttributeMaxDynamicSharedMemorySize, smem128);
    cudaFuncSetAttribute(scan_kernel,  cudaFuncAttributeMaxDynamicSharedMemorySize, smem128);

    embed_kernel<<<(RT * ES) / 256, 256>>>(x, pea, pet, embW, embB);

    // layer 0
    gi_gemm<64><<<RT / 128, 512, smem64>>>(Wih0, bih);
    scan_kernel<<<Mm / 32, 512, smem128>>>(Whh, bhh, hid);
    // layer 1
    gi_gemm<128><<<RT / 128, 512, smem128>>>(WihR, bih + G3);
    scan_kernel<<<Mm / 32, 512, smem128>>>(Whh + (size_t)G3 * HS, bhh + G3,
                                           hid + (size_t)Bb * HS);
    // layer 2
    gi_gemm<128><<<RT / 128, 512, smem128>>>(WihR + (size_t)G3 * HS, bih + 2 * G3);
    scan_kernel<<<Mm / 32, 512, smem128>>>(Whh + (size_t)2 * G3 * HS, bhh + 2 * G3,
                                           hid + (size_t)2 * Bb * HS);

    out_kernel<<<(Mm * 64) / 256, 256>>>(outW, outB, out);
}